// round 16
// baseline (speedup 1.0000x reference)
#include <cuda_runtime.h>
#include <cuda_fp16.h>
#include <stdint.h>

#define NNODES  100000
#define E_TOTAL 500000
#define MT      64
#define NTHR    256
#define LN_EPS  1e-5f

// ---------------- smem layout (bytes) ----------------
#define RA(s)    ((s)*8192)
#define RB(s)    (24576 + (s)*32768)
#define A2CH(ch)   ((ch)*8192)
#define B2SLOT(s2) (32768 + (s2)*16384)
#define L3P        0
#define CB    98304
#define B1S   (CB)
#define G1S   (CB+1024)
#define BE1S  (CB+2048)
#define B2S   (CB+3072)
#define G2S   (CB+3584)
#define BE2S  (CB+4096)
#define W3S   (CB+4608)
#define B3S   (CB+7168)
#define RBFMU (CB+7200)
#define SIDX  (CB+7296)
#define EIDX  (CB+7552)
#define PSUM  (CB+7808)
#define PSQ   (CB+8832)
#define MBAR  (CB+9856)
#define SMEM_TOTAL (CB+9920)               /* 108224 -> 2 CTAs/SM */

__device__ __align__(16) __half g_h16[NNODES*256];
__device__ __align__(16) unsigned char g_W1p[9*32768];
__device__ __align__(16) unsigned char g_W2p[4*16384];

static __device__ __forceinline__ uint32_t smem_u32(const void* p) {
    uint32_t a;
    asm("{ .reg .u64 t; cvta.to.shared.u64 t, %1; cvt.u32.u64 %0, t; }" : "=r"(a) : "l"(p));
    return a;
}
static __device__ __forceinline__ uint32_t hpack2(float a, float b) {
    return (uint32_t)__half_as_ushort(__float2half_rn(a)) |
           ((uint32_t)__half_as_ushort(__float2half_rn(b)) << 16);
}
static __device__ __forceinline__ void ldsm4(uint32_t* r, uint32_t addr) {
    asm volatile("ldmatrix.sync.aligned.m8n8.x4.shared.b16 {%0,%1,%2,%3}, [%4];"
                 : "=r"(r[0]), "=r"(r[1]), "=r"(r[2]), "=r"(r[3]) : "r"(addr));
}
static __device__ __forceinline__ void mma_h(float* c, const uint32_t* a,
                                             uint32_t b0, uint32_t b1) {
    asm volatile("mma.sync.aligned.m16n8k16.row.col.f32.f16.f16.f32 "
                 "{%0,%1,%2,%3}, {%4,%5,%6,%7}, {%8,%9}, {%0,%1,%2,%3};"
                 : "+f"(c[0]), "+f"(c[1]), "+f"(c[2]), "+f"(c[3])
                 : "r"(a[0]), "r"(a[1]), "r"(a[2]), "r"(a[3]), "r"(b0), "r"(b1));
}
static __device__ __forceinline__ void cpa16(uint32_t dst, const void* src) {
    asm volatile("cp.async.ca.shared.global [%0], [%1], 16;" :: "r"(dst), "l"(src) : "memory");
}
#define CP_COMMIT() asm volatile("cp.async.commit_group;" ::: "memory")
#define CP_WAIT1()  asm volatile("cp.async.wait_group 1;" ::: "memory")
#define CP_WAIT0()  asm volatile("cp.async.wait_group 0;" ::: "memory")

#define MBAR_INIT(a, c) \
    asm volatile("mbarrier.init.shared.b64 [%0], %1;" :: "r"((uint32_t)(a)), "r"((uint32_t)(c)) : "memory")
#define MBAR_EXPECT(a, b) \
    asm volatile("mbarrier.arrive.expect_tx.shared.b64 _, [%0], %1;" :: "r"((uint32_t)(a)), "r"((uint32_t)(b)) : "memory")
static __device__ __forceinline__ void bulk_g2s(uint32_t dst, const void* src,
                                                uint32_t bytes, uint32_t mbar) {
    asm volatile("cp.async.bulk.shared::cluster.global.mbarrier::complete_tx::bytes "
                 "[%0], [%1], %2, [%3];"
                 :: "r"(dst), "l"(src), "r"(bytes), "r"(mbar) : "memory");
}
static __device__ __forceinline__ void mbar_wait(uint32_t addr, uint32_t parity) {
    asm volatile(
        "{\n\t.reg .pred P;\n\t"
        "WL_%=:\n\t"
        "mbarrier.try_wait.parity.shared.b64 P, [%0], %1;\n\t"
        "@P bra.uni WD_%=;\n\t"
        "bra.uni WL_%=;\n\t"
        "WD_%=:\n\t}"
        :: "r"(addr), "r"(parity) : "memory");
}

static __device__ __forceinline__ float silu_f(float v) {
    return __fdividef(v, 1.0f + __expf(-v));
}

// ================= prep + padding kernels =================
__global__ void prep_h(const float* __restrict__ h) {
    const int t = blockIdx.x * blockDim.x + threadIdx.x;
    const float4 v0 = *(const float4*)(h + (size_t)t*8);
    const float4 v1 = *(const float4*)(h + (size_t)t*8 + 4);
    uint4 o;
    o.x = hpack2(v0.x, v0.y); o.y = hpack2(v0.z, v0.w);
    o.z = hpack2(v1.x, v1.y); o.w = hpack2(v1.z, v1.w);
    *(uint4*)(g_h16 + (size_t)t*8) = o;
}

__global__ void prep_w(const float* __restrict__ W1, const float* __restrict__ W2) {
    const int t = blockIdx.x * blockDim.x + threadIdx.x;
    if (t < 9*256*8) {
        const int c = t >> 11, rem = t & 2047, n = rem >> 3, s = rem & 7;
        uint4 H;
        uint32_t* hp = (uint32_t*)&H;
        #pragma unroll
        for (int p = 0; p < 4; p++) {
            const int k0 = c*64 + s*8 + p*2;
            const float w0 = (k0   < 551) ? W1[(size_t)k0*256 + n]     : 0.0f;
            const float w1 = (k0+1 < 551) ? W1[(size_t)(k0+1)*256 + n] : 0.0f;
            hp[p] = hpack2(w0, w1);
        }
        const uint32_t off = (uint32_t)n*128 + (uint32_t)((s ^ (n & 7)) << 4);
        *(uint4*)(g_W1p + (size_t)c*32768 + off) = H;
    } else if (t - 9*256*8 < 4*128*8) {
        const int t2 = t - 9*256*8;
        const int c = t2 >> 10, rem = t2 & 1023, n = rem >> 3, s = rem & 7;
        uint4 H;
        uint32_t* hp = (uint32_t*)&H;
        #pragma unroll
        for (int p = 0; p < 4; p++) {
            const int k0 = c*64 + s*8 + p*2;
            hp[p] = hpack2(W2[(size_t)k0*128 + n], W2[(size_t)(k0+1)*128 + n]);
        }
        const uint32_t off = (uint32_t)n*128 + (uint32_t)((s ^ (n & 7)) << 4);
        *(uint4*)(g_W2p + (size_t)c*16384 + off) = H;
    }
}

__global__ void pad_launch_k() {}

// ================= main kernel =================
__global__ __launch_bounds__(NTHR, 2)
void edgehead_mma(
    const float* __restrict__ x,
    const int* __restrict__ spawn_idx, const int* __restrict__ exist_idx,
    const float* __restrict__ ins_x, const int* __restrict__ ins_a,
    const int* __restrict__ ins_c,
    const float* __restrict__ b1, const float* __restrict__ g1, const float* __restrict__ be1,
    const float* __restrict__ b2, const float* __restrict__ g2, const float* __restrict__ be2,
    const float* __restrict__ W3, const float* __restrict__ b3,
    const float* __restrict__ rbf_mu, const float* __restrict__ rbf_gamma,
    float* __restrict__ out)
{
    extern __shared__ char smc[];
    const uint32_t sb = smem_u32(smc);
    const int tid  = threadIdx.x;
    const int lane = tid & 31;
    const int wrp  = tid >> 5;
    const int warp_m = wrp & 1;          // 2 m-warps x 32 rows
    const int warp_n = wrp >> 1;         // 4 n-warps
    const int m0w = warp_m * 32;
    const int e0  = blockIdx.x * MT;
    const int mcount = min(MT, E_TOTAL - e0);

    // ---- direct-index A gathers for chunks 0,1 ----
    #pragma unroll
    for (int c = 0; c < 2; c++) {
        #pragma unroll
        for (int i = 0; i < 2; i++) {
            const int g = tid + i*NTHR;
            const int m = g >> 3, s = g & 7;
            const int e = e0 + (m < mcount ? m : 0);
            const int idx = spawn_idx[e];
            cpa16(sb + RA(c) + (uint32_t)m*128 + (uint32_t)((s ^ (m & 7)) << 4),
                  g_h16 + (size_t)idx*256 + c*64 + s*8);
        }
        CP_COMMIT();
    }

    // ---- stage constants + indices; init mbarriers ----
    ((float*)(smc + B1S))[tid]  = b1[tid];
    ((float*)(smc + G1S))[tid]  = g1[tid];
    ((float*)(smc + BE1S))[tid] = be1[tid];
    if (tid < 128) {
        ((float*)(smc + B2S))[tid]  = b2[tid];
        ((float*)(smc + G2S))[tid]  = g2[tid];
        ((float*)(smc + BE2S))[tid] = be2[tid];
    }
    if (tid < MT) {
        const int e = e0 + (tid < mcount ? tid : 0);
        ((int*)(smc + SIDX))[tid] = spawn_idx[e];
        ((int*)(smc + EIDX))[tid] = exist_idx[e];
    }
    for (int i = tid; i < 640; i += NTHR) ((float*)(smc + W3S))[i] = W3[i];
    if (tid < 5)  ((float*)(smc + B3S))[tid] = b3[tid];
    if (tid < 16) ((float*)(smc + RBFMU))[tid] = rbf_mu[tid];
    if (tid == 0) {
        #pragma unroll
        for (int i = 0; i < 6; i++) MBAR_INIT(sb + MBAR + i*8, 1);
    }
    __syncthreads();

    // ---- launch B1 bulk chunks 0,1 ----
    if (tid == 0) {
        #pragma unroll
        for (int s = 0; s < 2; s++) {
            MBAR_EXPECT(sb + MBAR + s*8, 32768);
            bulk_g2s(sb + RB(s), g_W1p + (size_t)s*32768, 32768, sb + MBAR + s*8);
        }
    }

    // ---- RBF raw inputs into registers ----
    float p0=0.f, p1=0.f, p2=0.f, q0=0.f, q1=0.f, q2=0.f, gma=0.f;
    int ia = 0, ic = 0;
    if (tid < MT) {
        const int e = e0 + (tid < mcount ? tid : 0);
        const int ie = ((const int*)(smc + EIDX))[tid];
        p0 = ins_x[e*3+0]; p1 = ins_x[e*3+1]; p2 = ins_x[e*3+2];
        q0 = x[ie*3+0];    q1 = x[ie*3+1];    q2 = x[ie*3+2];
        gma = rbf_gamma[0];
        ia = ins_a[e]; ic = ins_c[e];
    }

    const int* sidx = (const int*)(smc + SIDX);
    const int* eidx = (const int*)(smc + EIDX);
    auto issueA = [&](int c, int st) {
        const int* idxarr = (c < 4) ? sidx : eidx;
        const int cbase = (c & 3) * 64;
        #pragma unroll
        for (int i = 0; i < 2; i++) {
            const int g = tid + i*NTHR;
            const int m = g >> 3, s = g & 7;
            const __half* src = g_h16 + (size_t)idxarr[m]*256 + cbase + s*8;
            cpa16(sb + RA(st) + (uint32_t)m*128 + (uint32_t)((s ^ (m & 7)) << 4), src);
        }
    };

    // ---- ldmatrix per-lane addressing (seg-XOR swizzle) ----
    const int lt  = lane >> 3;
    const int ar  = (lane & 7) + ((lt & 1) << 3);
    const int s0a = lt >> 1;
    const int nr  = (lane & 7) + ((lt >> 1) << 3);
    const int s0b = lt & 1;
    const int rx  = lane & 7;
    const uint32_t aro0 = (uint32_t)(m0w + ar) * 128;
    const uint32_t aro1 = aro0 + 16*128;
    const uint32_t bro1 = (uint32_t)(warp_n*64 + nr) * 128;
    const uint32_t bro2 = (uint32_t)(warp_n*32 + nr) * 128;
    // swizzle offset helpers (seg index ks*2 + s0)
    #define XA(ks) ((uint32_t)((((ks)*2 + s0a) ^ rx) << 4))
    #define XB(ks) ((uint32_t)((((ks)*2 + s0b) ^ rx) << 4))

    // ================= layer 1: software-pipelined MMA loop =================
    float acc[2][8][4];
    #pragma unroll
    for (int a = 0; a < 2; a++)
        #pragma unroll
        for (int i = 0; i < 8; i++)
            #pragma unroll
            for (int j = 0; j < 4; j++) acc[a][i][j] = 0.0f;

    int s3 = 0;   // c % 3
    for (int c = 0; c < 9; c++) {
        if (c <= 6) { CP_WAIT1(); } else { CP_WAIT0(); }
        mbar_wait(sb + MBAR + (c & 1)*8, (c >> 1) & 1);
        __syncthreads();   // MMA(c-1) fully done -> A stage (c+2)%3 free
        if (c <= 5) {
            const int st = (s3 == 0) ? 2 : s3 - 1;
            issueA(c + 2, st); CP_COMMIT();
        } else if (c == 6) {
            if (tid < MT) {
                const float* mus = (const float*)(smc + RBFMU);
                const float dx = p0 - q0, dy = p1 - q1, dz = p2 - q2;
                const float dval = fmaxf(sqrtf(dx*dx + dy*dy + dz*dz), 1e-6f);
                const int m = tid;
                const uint32_t rxm = (uint32_t)(m & 7);
                #pragma unroll
                for (int s = 0; s < 8; s++) {
                    uint4 H;
                    uint32_t* hp = (uint32_t*)&H;
                    #pragma unroll
                    for (int p = 0; p < 4; p++) {
                        const int j0 = s*8 + p*2, j1 = j0 + 1;
                        float v0, v1;
                        if (j0 < 16) {
                            const float t0 = dval - mus[j0], t1 = dval - mus[j1];
                            v0 = __expf(-gma*t0*t0); v1 = __expf(-gma*t1*t1);
                        } else {
                            v0 = (j0 == 16 + ia || j0 == 32 + ic) ? 1.0f : 0.0f;
                            v1 = (j1 == 16 + ia || j1 == 32 + ic) ? 1.0f : 0.0f;
                        }
                        hp[p] = hpack2(v0, v1);
                    }
                    *(uint4*)(smc + RA(2) + (uint32_t)m*128
                              + (uint32_t)(((uint32_t)s ^ rxm) << 4)) = H;
                }
            }
        }
        const uint32_t Ab = sb + RA(s3);
        const uint32_t Bb = sb + RB(c & 1);
        // --- pipelined 16-iteration flat loop (ks = i>>2, nt = i&3) ---
        {
            uint32_t aC[8], aN[8], bC[4], bN[4];
            ldsm4(aC,     Ab + aro0 + XA(0));
            ldsm4(aC + 4, Ab + aro1 + XA(0));
            ldsm4(bC,     Bb + bro1 + XB(0));
            #pragma unroll
            for (int i = 0; i < 16; i++) {
                const int nt = i & 3;
                if (i < 15) {
                    const int ks1 = (i + 1) >> 2, nt1 = (i + 1) & 3;
                    ldsm4(bN, Bb + bro1 + (uint32_t)nt1*2048 + XB(ks1));
                    if (nt == 3) {
                        ldsm4(aN,     Ab + aro0 + XA(ks1));
                        ldsm4(aN + 4, Ab + aro1 + XA(ks1));
                    }
                }
                mma_h(acc[0][nt*2],   aC,     bC[0], bC[1]);
                mma_h(acc[0][nt*2+1], aC,     bC[2], bC[3]);
                mma_h(acc[1][nt*2],   aC + 4, bC[0], bC[1]);
                mma_h(acc[1][nt*2+1], aC + 4, bC[2], bC[3]);
                #pragma unroll
                for (int r = 0; r < 4; r++) bC[r] = bN[r];
                if (nt == 3) {
                    #pragma unroll
                    for (int r = 0; r < 8; r++) aC[r] = aN[r];
                }
            }
        }
        __syncthreads();   // B stage c&1 fully consumed before overwrite
        if (c <= 6) {
            if (tid == 0) {
                MBAR_EXPECT(sb + MBAR + (c & 1)*8, 32768);
                bulk_g2s(sb + RB(c & 1), g_W1p + (size_t)(c + 2)*32768, 32768,
                         sb + MBAR + (c & 1)*8);
            }
        } else if (c == 7) {
            if (tid == 0) {
                #pragma unroll
                for (int s2 = 2; s2 < 4; s2++) {
                    MBAR_EXPECT(sb + MBAR + 16 + s2*8, 16384);
                    bulk_g2s(sb + B2SLOT(s2), g_W2p + (size_t)s2*16384, 16384,
                             sb + MBAR + 16 + s2*8);
                }
            }
        }
        s3 = (s3 == 2) ? 0 : s3 + 1;
    }

    // ================= epilogue 1: +b1, LN(256), SiLU -> A2 fp16 =================
    {
        const float* b1s  = (const float*)(smc + B1S);
        const float* g1s  = (const float*)(smc + G1S);
        const float* be1s = (const float*)(smc + BE1S);
        float* psum = (float*)(smc + PSUM);
        float* psq  = (float*)(smc + PSQ);
        const int g = lane >> 2, tig = lane & 3;
        float S[2][2] = {{0,0},{0,0}}, Q[2][2] = {{0,0},{0,0}};
        #pragma unroll
        for (int mb = 0; mb < 2; mb++)
            #pragma unroll
            for (int nt = 0; nt < 8; nt++) {
                const int n = warp_n*64 + nt*8 + tig*2;
                const float bn0 = b1s[n], bn1 = b1s[n+1];
                acc[mb][nt][0] += bn0; acc[mb][nt][1] += bn1;
                acc[mb][nt][2] += bn0; acc[mb][nt][3] += bn1;
                S[mb][0] += acc[mb][nt][0] + acc[mb][nt][1];
                Q[mb][0] += acc[mb][nt][0]*acc[mb][nt][0] + acc[mb][nt][1]*acc[mb][nt][1];
                S[mb][1] += acc[mb][nt][2] + acc[mb][nt][3];
                Q[mb][1] += acc[mb][nt][2]*acc[mb][nt][2] + acc[mb][nt][3]*acc[mb][nt][3];
            }
        #pragma unroll
        for (int off = 1; off <= 2; off <<= 1)
            #pragma unroll
            for (int mb = 0; mb < 2; mb++)
                #pragma unroll
                for (int hh = 0; hh < 2; hh++) {
                    S[mb][hh] += __shfl_xor_sync(~0u, S[mb][hh], off);
                    Q[mb][hh] += __shfl_xor_sync(~0u, Q[mb][hh], off);
                }
        if (tig == 0) {
            #pragma unroll
            for (int mb = 0; mb < 2; mb++)
                #pragma unroll
                for (int hh = 0; hh < 2; hh++) {
                    const int row = m0w + mb*16 + g + hh*8;
                    psum[row*4 + warp_n] = S[mb][hh];
                    psq[row*4 + warp_n]  = Q[mb][hh];
                }
        }
        __syncthreads();   // psum exchange; MMA(8) globally complete past here
        if (tid == 0) {
            #pragma unroll
            for (int s2 = 0; s2 < 2; s2++) {
                MBAR_EXPECT(sb + MBAR + 16 + s2*8, 16384);
                bulk_g2s(sb + B2SLOT(s2), g_W2p + (size_t)s2*16384, 16384,
                         sb + MBAR + 16 + s2*8);
            }
        }
        float mean[2][2], rstd[2][2];
        #pragma unroll
        for (int mb = 0; mb < 2; mb++)
            #pragma unroll
            for (int hh = 0; hh < 2; hh++) {
                const int row = m0w + mb*16 + g + hh*8;
                const float s4 = psum[row*4+0] + psum[row*4+1] + psum[row*4+2] + psum[row*4+3];
                const float q4 = psq[row*4+0] + psq[row*4+1] + psq[row*4+2] + psq[row*4+3];
                mean[mb][hh] = s4 * (1.0f/256.0f);
                rstd[mb][hh] = rsqrtf(q4 * (1.0f/256.0f) - mean[mb][hh]*mean[mb][hh] + LN_EPS);
            }
        #pragma unroll
        for (int mb = 0; mb < 2; mb++)
            #pragma unroll
            for (int nt = 0; nt < 8; nt++) {
                const int n = warp_n*64 + nt*8 + tig*2;
                const float ga = g1s[n], gb = g1s[n+1], ba = be1s[n], bb = be1s[n+1];
                #pragma unroll
                for (int hh = 0; hh < 2; hh++) {
                    const int row = m0w + mb*16 + g + hh*8;
                    const float v0 = silu_f((acc[mb][nt][hh*2+0] - mean[mb][hh])*rstd[mb][hh]*ga + ba);
                    const float v1 = silu_f((acc[mb][nt][hh*2+1] - mean[mb][hh])*rstd[mb][hh]*gb + bb);
                    const uint32_t ad = (uint32_t)A2CH(warp_n) + (uint32_t)row*128
                                        + (uint32_t)((nt ^ (row & 7)) << 4) + (uint32_t)tig*4;
                    *(uint32_t*)(smc + ad) = hpack2(v0, v1);
                }
            }
    }
    __syncthreads();   // A2 visible before layer-2 ldsm

    // ================= layer 2: pipelined, slots in order {2,3,0,1} ==============
    float acc2[2][4][4];
    #pragma unroll
    for (int a = 0; a < 2; a++)
        #pragma unroll
        for (int i = 0; i < 4; i++)
            #pragma unroll
            for (int j = 0; j < 4; j++) acc2[a][i][j] = 0.0f;

    const int order[4] = {2, 3, 0, 1};
    #pragma unroll
    for (int oi = 0; oi < 4; oi++) {
        const int c2 = order[oi];
        mbar_wait(sb + MBAR + 16 + c2*8, 0);
        const uint32_t Ab = sb + A2CH(c2);
        const uint32_t Bb = sb + B2SLOT(c2);
        uint32_t aC[8], aN[8], bC[4], bN[4];
        ldsm4(aC,     Ab + aro0 + XA(0));
        ldsm4(aC + 4, Ab + aro1 + XA(0));
        ldsm4(bC,     Bb + bro2 + XB(0));
        #pragma unroll
        for (int i = 0; i < 8; i++) {          // ks = i>>1, nt = i&1
            const int nt = i & 1;
            if (i < 7) {
                const int ks1 = (i + 1) >> 1, nt1 = (i + 1) & 1;
                ldsm4(bN, Bb + bro2 + (uint32_t)nt1*2048 + XB(ks1));
                if (nt == 1) {
                    ldsm4(aN,     Ab + aro0 + XA(ks1));
                    ldsm4(aN + 4, Ab + aro1 + XA(ks1));
                }
            }
            mma_h(acc2[0][nt*2],   aC,     bC[0], bC[1]);
            mma_h(acc2[0][nt*2+1], aC,     bC[2], bC[3]);
            mma_h(acc2[1][nt*2],   aC + 4, bC[0], bC[1]);
            mma_h(acc2[1][nt*2+1], aC + 4, bC[2], bC[3]);
            #pragma unroll
            for (int r = 0; r < 4; r++) bC[r] = bN[r];
            if (nt == 1) {
                #pragma unroll
                for (int r = 0; r < 8; r++) aC[r] = aN[r];
            }
        }
    }

    // ========== epilogue 2: +b2, LN(128), SiLU, FUSED layer-3 partials ==========
    {
        const float* b2s  = (const float*)(smc + B2S);
        const float* g2s  = (const float*)(smc + G2S);
        const float* be2s = (const float*)(smc + BE2S);
        const float* w3s  = (const float*)(smc + W3S);
        float* psum = (float*)(smc + PSUM);
        float* psq  = (float*)(smc + PSQ);
        float* l3p  = (float*)(smc + L3P);
        const int g = lane >> 2, tig = lane & 3;
        float S[2][2] = {{0,0},{0,0}}, Q[2][2] = {{0,0},{0,0}};
        #pragma unroll
        for (int mb = 0; mb < 2; mb++)
            #pragma unroll
            for (int nt = 0; nt < 4; nt++) {
                const int n = warp_n*32 + nt*8 + tig*2;
                const float bn0 = b2s[n], bn1 = b2s[n+1];
                acc2[mb][nt][0] += bn0; acc2[mb][nt][1] += bn1;
                acc2[mb][nt][2] += bn0; acc2[mb][nt][3] += bn1;
                S[mb][0] += acc2[mb][nt][0] + acc2[mb][nt][1];
                Q[mb][0] += acc2[mb][nt][0]*acc2[mb][nt][0] + acc2[mb][nt][1]*acc2[mb][nt][1];
                S[mb][1] += acc2[mb][nt][2] + acc2[mb][nt][3];
                Q[mb][1] += acc2[mb][nt][2]*acc2[mb][nt][2] + acc2[mb][nt][3]*acc2[mb][nt][3];
            }
        #pragma unroll
        for (int off = 1; off <= 2; off <<= 1)
            #pragma unroll
            for (int mb = 0; mb < 2; mb++)
                #pragma unroll
                for (int hh = 0; hh < 2; hh++) {
                    S[mb][hh] += __shfl_xor_sync(~0u, S[mb][hh], off);
                    Q[mb][hh] += __shfl_xor_sync(~0u, Q[mb][hh], off);
                }
        if (tig == 0) {
            #pragma unroll
            for (int mb = 0; mb < 2; mb++)
                #pragma unroll
                for (int hh = 0; hh < 2; hh++) {
                    const int row = m0w + mb*16 + g + hh*8;
                    psum[row*4 + warp_n] = S[mb][hh];
                    psq[row*4 + warp_n]  = Q[mb][hh];
                }
        }
        __syncthreads();   // psum exchange; all layer-2 ldsm done -> L3P free
        float o[2][2][5];
        #pragma unroll
        for (int mb = 0; mb < 2; mb++)
            #pragma unroll
            for (int hh = 0; hh < 2; hh++)
                #pragma unroll
                for (int j = 0; j < 5; j++) o[mb][hh][j] = 0.0f;
        #pragma unroll
        for (int mb = 0; mb < 2; mb++)
            #pragma unroll
            for (int hh = 0; hh < 2; hh++) {
                const int row = m0w + mb*16 + g + hh*8;
                const float s4 = psum[row*4+0] + psum[row*4+1] + psum[row*4+2] + psum[row*4+3];
                const float q4 = psq[row*4+0] + psq[row*4+1] + psq[row*4+2] + psq[row*4+3];
                const float mean = s4 * (1.0f/128.0f);
                const float rstd = rsqrtf(q4 * (1.0f/128.0f) - mean*mean + LN_EPS);
                #pragma unroll
                for (int nt = 0; nt < 4; nt++) {
                    const int n = warp_n*32 + nt*8 + tig*2;
                    const float v0 = silu_f((acc2[mb][nt][hh*2+0] - mean)*rstd*g2s[n]   + be2s[n]);
                    const float v1 = silu_f((acc2[mb][nt][hh*2+1] - mean)*rstd*g2s[n+1] + be2s[n+1]);
                    const float* w0 = w3s + n*5;
                    #pragma unroll
                    for (int j = 0; j < 5; j++)
                        o[mb][hh][j] += v0*w0[j] + v1*w0[5 + j];
                }
            }
        #pragma unroll
        for (int off = 1; off <= 2; off <<= 1)
            #pragma unroll
            for (int mb = 0; mb < 2; mb++)
                #pragma unroll
                for (int hh = 0; hh < 2; hh++)
                    #pragma unroll
                    for (int j = 0; j < 5; j++)
                        o[mb][hh][j] += __shfl_xor_sync(~0u, o[mb][hh][j], off);
        if (tig == 0) {
            #pragma unroll
            for (int mb = 0; mb < 2; mb++)
                #pragma unroll
                for (int hh = 0; hh < 2; hh++) {
                    const int row = m0w + mb*16 + g + hh*8;
                    float* dst = l3p + row*20 + warp_n*5;
                    #pragma unroll
                    for (int j = 0; j < 5; j++) dst[j] = o[mb][hh][j];
                }
        }
    }
    __syncthreads();

    // ---- final: sum 4 warp-partials + b3, store ----
    if (tid < MT && tid < mcount) {
        const float* l3p = (const float*)(smc + L3P);
        const float* b3s = (const float*)(smc + B3S);
        const float* pr  = l3p + tid*20;
        float* op = out + (size_t)(e0 + tid)*5;
        #pragma unroll
        for (int j = 0; j < 5; j++)
            op[j] = b3s[j] + pr[j] + pr[5 + j] + pr[10 + j] + pr[15 + j];
    }
    #undef XA
    #undef XB
}

extern "C" void kernel_launch(void* const* d_in, const int* in_sizes, int n_in,
                              void* d_out, int out_size)
{
    const float* h         = (const float*)d_in[0];
    const float* x         = (const float*)d_in[1];
    const int*   spawn_idx = (const int*)d_in[2];
    const int*   exist_idx = (const int*)d_in[3];
    const float* ins_x     = (const float*)d_in[4];
    const int*   ins_a     = (const int*)d_in[5];
    const int*   ins_c     = (const int*)d_in[6];
    const float* W1        = (const float*)d_in[7];
    const float* b1        = (const float*)d_in[8];
    const float* g1        = (const float*)d_in[9];
    const float* be1       = (const float*)d_in[10];
    const float* W2        = (const float*)d_in[11];
    const float* b2        = (const float*)d_in[12];
    const float* g2        = (const float*)d_in[13];
    const float* be2       = (const float*)d_in[14];
    const float* W3        = (const float*)d_in[15];
    const float* b3        = (const float*)d_in[16];
    const float* rbf_mu    = (const float*)d_in[17];
    const float* rbf_gamma = (const float*)d_in[18];
    float* out = (float*)d_out;

    prep_h<<<NNODES*32/256, 256>>>(h);
    prep_w<<<(9*256*8 + 4*128*8 + 255)/256, 256>>>(W1, W2);
    pad_launch_k<<<1, 32>>>();

    cudaFuncSetAttribute(edgehead_mma,
                         cudaFuncAttributeMaxDynamicSharedMemorySize, SMEM_TOTAL);
    const int grid = (E_TOTAL + MT - 1) / MT;   // 7813
    edgehead_mma<<<grid, NTHR, SMEM_TOTAL>>>(
        x, spawn_idx, exist_idx, ins_x, ins_a, ins_c,
        b1, g1, be1, b2, g2, be2, W3, b3, rbf_mu, rbf_gamma, out);
}

// round 17
// speedup vs baseline: 1.0019x; 1.0019x over previous
#include <cuda_runtime.h>
#include <cuda_fp16.h>
#include <stdint.h>

#define NNODES  100000
#define E_TOTAL 500000
#define MT      64
#define NTHR    256
#define LN_EPS  1e-5f

// ---------------- smem layout (bytes) ----------------
#define RA(s)    ((s)*8192)
#define RB(s)    (24576 + (s)*32768)
#define A2CH(ch)   ((ch)*8192)
#define B2SLOT(s2) (32768 + (s2)*16384)
#define L3P        0
#define CB    98304
#define B1S   (CB)
#define G1S   (CB+1024)
#define BE1S  (CB+2048)
#define B2S   (CB+3072)
#define G2S   (CB+3584)
#define BE2S  (CB+4096)
#define W3S   (CB+4608)
#define B3S   (CB+7168)
#define RBFMU (CB+7200)
#define SIDX  (CB+7296)
#define EIDX  (CB+7552)
#define PSUM  (CB+7808)
#define PSQ   (CB+8832)
#define MBAR  (CB+9856)
#define SMEM_TOTAL (CB+9920)               /* 108224 -> 2 CTAs/SM */

__device__ __align__(16) __half g_h16[NNODES*256];
__device__ __align__(16) unsigned char g_W1p[9*32768];
__device__ __align__(16) unsigned char g_W2p[4*16384];

static __device__ __forceinline__ uint32_t smem_u32(const void* p) {
    uint32_t a;
    asm("{ .reg .u64 t; cvta.to.shared.u64 t, %1; cvt.u32.u64 %0, t; }" : "=r"(a) : "l"(p));
    return a;
}
static __device__ __forceinline__ uint32_t hpack2(float a, float b) {
    return (uint32_t)__half_as_ushort(__float2half_rn(a)) |
           ((uint32_t)__half_as_ushort(__float2half_rn(b)) << 16);
}
static __device__ __forceinline__ void ldsm4(uint32_t* r, uint32_t addr) {
    asm volatile("ldmatrix.sync.aligned.m8n8.x4.shared.b16 {%0,%1,%2,%3}, [%4];"
                 : "=r"(r[0]), "=r"(r[1]), "=r"(r[2]), "=r"(r[3]) : "r"(addr));
}
static __device__ __forceinline__ void mma_h(float* c, const uint32_t* a,
                                             uint32_t b0, uint32_t b1) {
    asm volatile("mma.sync.aligned.m16n8k16.row.col.f32.f16.f16.f32 "
                 "{%0,%1,%2,%3}, {%4,%5,%6,%7}, {%8,%9}, {%0,%1,%2,%3};"
                 : "+f"(c[0]), "+f"(c[1]), "+f"(c[2]), "+f"(c[3])
                 : "r"(a[0]), "r"(a[1]), "r"(a[2]), "r"(a[3]), "r"(b0), "r"(b1));
}
static __device__ __forceinline__ void cpa16(uint32_t dst, const void* src) {
    asm volatile("cp.async.ca.shared.global [%0], [%1], 16;" :: "r"(dst), "l"(src) : "memory");
}
#define CP_COMMIT() asm volatile("cp.async.commit_group;" ::: "memory")
#define CP_WAIT1()  asm volatile("cp.async.wait_group 1;" ::: "memory")
#define CP_WAIT0()  asm volatile("cp.async.wait_group 0;" ::: "memory")

#define MBAR_INIT(a, c) \
    asm volatile("mbarrier.init.shared.b64 [%0], %1;" :: "r"((uint32_t)(a)), "r"((uint32_t)(c)) : "memory")
#define MBAR_EXPECT(a, b) \
    asm volatile("mbarrier.arrive.expect_tx.shared.b64 _, [%0], %1;" :: "r"((uint32_t)(a)), "r"((uint32_t)(b)) : "memory")
static __device__ __forceinline__ void bulk_g2s(uint32_t dst, const void* src,
                                                uint32_t bytes, uint32_t mbar) {
    asm volatile("cp.async.bulk.shared::cluster.global.mbarrier::complete_tx::bytes "
                 "[%0], [%1], %2, [%3];"
                 :: "r"(dst), "l"(src), "r"(bytes), "r"(mbar) : "memory");
}
static __device__ __forceinline__ void mbar_wait(uint32_t addr, uint32_t parity) {
    asm volatile(
        "{\n\t.reg .pred P;\n\t"
        "WL_%=:\n\t"
        "mbarrier.try_wait.parity.shared.b64 P, [%0], %1;\n\t"
        "@P bra.uni WD_%=;\n\t"
        "bra.uni WL_%=;\n\t"
        "WD_%=:\n\t}"
        :: "r"(addr), "r"(parity) : "memory");
}

static __device__ __forceinline__ float silu_f(float v) {
    return __fdividef(v, 1.0f + __expf(-v));
}

// ================= prep + padding kernels =================
__global__ void prep_h(const float* __restrict__ h) {
    const int t = blockIdx.x * blockDim.x + threadIdx.x;
    const float4 v0 = *(const float4*)(h + (size_t)t*8);
    const float4 v1 = *(const float4*)(h + (size_t)t*8 + 4);
    uint4 o;
    o.x = hpack2(v0.x, v0.y); o.y = hpack2(v0.z, v0.w);
    o.z = hpack2(v1.x, v1.y); o.w = hpack2(v1.z, v1.w);
    *(uint4*)(g_h16 + (size_t)t*8) = o;
}

__global__ void prep_w(const float* __restrict__ W1, const float* __restrict__ W2) {
    const int t = blockIdx.x * blockDim.x + threadIdx.x;
    if (t < 9*256*8) {
        const int c = t >> 11, rem = t & 2047, n = rem >> 3, s = rem & 7;
        uint4 H;
        uint32_t* hp = (uint32_t*)&H;
        #pragma unroll
        for (int p = 0; p < 4; p++) {
            const int k0 = c*64 + s*8 + p*2;
            const float w0 = (k0   < 551) ? W1[(size_t)k0*256 + n]     : 0.0f;
            const float w1 = (k0+1 < 551) ? W1[(size_t)(k0+1)*256 + n] : 0.0f;
            hp[p] = hpack2(w0, w1);
        }
        const uint32_t off = (uint32_t)n*128 + (uint32_t)((s ^ (n & 7)) << 4);
        *(uint4*)(g_W1p + (size_t)c*32768 + off) = H;
    } else if (t - 9*256*8 < 4*128*8) {
        const int t2 = t - 9*256*8;
        const int c = t2 >> 10, rem = t2 & 1023, n = rem >> 3, s = rem & 7;
        uint4 H;
        uint32_t* hp = (uint32_t*)&H;
        #pragma unroll
        for (int p = 0; p < 4; p++) {
            const int k0 = c*64 + s*8 + p*2;
            hp[p] = hpack2(W2[(size_t)k0*128 + n], W2[(size_t)(k0+1)*128 + n]);
        }
        const uint32_t off = (uint32_t)n*128 + (uint32_t)((s ^ (n & 7)) << 4);
        *(uint4*)(g_W2p + (size_t)c*16384 + off) = H;
    }
}

__global__ void pad_launch_k() {}

// ================= main kernel =================
__global__ __launch_bounds__(NTHR, 2)
void edgehead_mma(
    const float* __restrict__ x,
    const int* __restrict__ spawn_idx, const int* __restrict__ exist_idx,
    const float* __restrict__ ins_x, const int* __restrict__ ins_a,
    const int* __restrict__ ins_c,
    const float* __restrict__ b1, const float* __restrict__ g1, const float* __restrict__ be1,
    const float* __restrict__ b2, const float* __restrict__ g2, const float* __restrict__ be2,
    const float* __restrict__ W3, const float* __restrict__ b3,
    const float* __restrict__ rbf_mu, const float* __restrict__ rbf_gamma,
    float* __restrict__ out)
{
    extern __shared__ char smc[];
    const uint32_t sb = smem_u32(smc);
    const int tid  = threadIdx.x;
    const int lane = tid & 31;
    const int wrp  = tid >> 5;
    const int warp_m = wrp & 1;          // 2 m-warps x 32 rows
    const int warp_n = wrp >> 1;         // 4 n-warps
    const int m0w = warp_m * 32;
    const int e0  = blockIdx.x * MT;
    const int mcount = min(MT, E_TOTAL - e0);

    // ---- direct-index A gathers for chunks 0,1 ----
    #pragma unroll
    for (int c = 0; c < 2; c++) {
        #pragma unroll
        for (int i = 0; i < 2; i++) {
            const int g = tid + i*NTHR;
            const int m = g >> 3, s = g & 7;
            const int e = e0 + (m < mcount ? m : 0);
            const int idx = spawn_idx[e];
            cpa16(sb + RA(c) + (uint32_t)m*128 + (uint32_t)((s ^ (m & 7)) << 4),
                  g_h16 + (size_t)idx*256 + c*64 + s*8);
        }
        CP_COMMIT();
    }

    // ---- stage constants + indices; init mbarriers ----
    ((float*)(smc + B1S))[tid]  = b1[tid];
    ((float*)(smc + G1S))[tid]  = g1[tid];
    ((float*)(smc + BE1S))[tid] = be1[tid];
    if (tid < 128) {
        ((float*)(smc + B2S))[tid]  = b2[tid];
        ((float*)(smc + G2S))[tid]  = g2[tid];
        ((float*)(smc + BE2S))[tid] = be2[tid];
    }
    if (tid < MT) {
        const int e = e0 + (tid < mcount ? tid : 0);
        ((int*)(smc + SIDX))[tid] = spawn_idx[e];
        ((int*)(smc + EIDX))[tid] = exist_idx[e];
    }
    for (int i = tid; i < 640; i += NTHR) ((float*)(smc + W3S))[i] = W3[i];
    if (tid < 5)  ((float*)(smc + B3S))[tid] = b3[tid];
    if (tid < 16) ((float*)(smc + RBFMU))[tid] = rbf_mu[tid];
    if (tid == 0) {
        #pragma unroll
        for (int i = 0; i < 6; i++) MBAR_INIT(sb + MBAR + i*8, 1);
    }
    __syncthreads();

    // ---- launch B1 bulk chunks 0,1 ----
    if (tid == 0) {
        #pragma unroll
        for (int s = 0; s < 2; s++) {
            MBAR_EXPECT(sb + MBAR + s*8, 32768);
            bulk_g2s(sb + RB(s), g_W1p + (size_t)s*32768, 32768, sb + MBAR + s*8);
        }
    }

    // ---- RBF raw inputs into registers ----
    float p0=0.f, p1=0.f, p2=0.f, q0=0.f, q1=0.f, q2=0.f, gma=0.f;
    int ia = 0, ic = 0;
    if (tid < MT) {
        const int e = e0 + (tid < mcount ? tid : 0);
        const int ie = ((const int*)(smc + EIDX))[tid];
        p0 = ins_x[e*3+0]; p1 = ins_x[e*3+1]; p2 = ins_x[e*3+2];
        q0 = x[ie*3+0];    q1 = x[ie*3+1];    q2 = x[ie*3+2];
        gma = rbf_gamma[0];
        ia = ins_a[e]; ic = ins_c[e];
    }

    const int* sidx = (const int*)(smc + SIDX);
    const int* eidx = (const int*)(smc + EIDX);
    auto issueA = [&](int c, int st) {
        const int* idxarr = (c < 4) ? sidx : eidx;
        const int cbase = (c & 3) * 64;
        #pragma unroll
        for (int i = 0; i < 2; i++) {
            const int g = tid + i*NTHR;
            const int m = g >> 3, s = g & 7;
            const __half* src = g_h16 + (size_t)idxarr[m]*256 + cbase + s*8;
            cpa16(sb + RA(st) + (uint32_t)m*128 + (uint32_t)((s ^ (m & 7)) << 4), src);
        }
    };

    // ---- ldmatrix per-lane addressing (seg-XOR swizzle) ----
    const int lt  = lane >> 3;
    const int ar  = (lane & 7) + ((lt & 1) << 3);
    const int s0a = lt >> 1;
    const int nr  = (lane & 7) + ((lt >> 1) << 3);
    const int s0b = lt & 1;
    const int rx  = lane & 7;
    const uint32_t aro0 = (uint32_t)(m0w + ar) * 128;
    const uint32_t aro1 = aro0 + 16*128;
    const uint32_t bro1 = (uint32_t)(warp_n*64 + nr) * 128;
    const uint32_t bro2 = (uint32_t)(warp_n*32 + nr) * 128;
    #define XA(ks) ((uint32_t)((((ks)*2 + s0a) ^ rx) << 4))
    #define XB(ks) ((uint32_t)((((ks)*2 + s0b) ^ rx) << 4))

    // ================= layer 1: distance-2 B prefetch pipeline =================
    float acc[2][8][4];
    #pragma unroll
    for (int a = 0; a < 2; a++)
        #pragma unroll
        for (int i = 0; i < 8; i++)
            #pragma unroll
            for (int j = 0; j < 4; j++) acc[a][i][j] = 0.0f;

    int s3 = 0;   // c % 3
    for (int c = 0; c < 9; c++) {
        if (c <= 6) { CP_WAIT1(); } else { CP_WAIT0(); }
        mbar_wait(sb + MBAR + (c & 1)*8, (c >> 1) & 1);
        __syncthreads();   // MMA(c-1) fully done -> A stage (c+2)%3 free
        if (c <= 5) {
            const int st = (s3 == 0) ? 2 : s3 - 1;
            issueA(c + 2, st); CP_COMMIT();
        } else if (c == 6) {
            if (tid < MT) {
                const float* mus = (const float*)(smc + RBFMU);
                const float dx = p0 - q0, dy = p1 - q1, dz = p2 - q2;
                const float dval = fmaxf(sqrtf(dx*dx + dy*dy + dz*dz), 1e-6f);
                const int m = tid;
                const uint32_t rxm = (uint32_t)(m & 7);
                #pragma unroll
                for (int s = 0; s < 8; s++) {
                    uint4 H;
                    uint32_t* hp = (uint32_t*)&H;
                    #pragma unroll
                    for (int p = 0; p < 4; p++) {
                        const int j0 = s*8 + p*2, j1 = j0 + 1;
                        float v0, v1;
                        if (j0 < 16) {
                            const float t0 = dval - mus[j0], t1 = dval - mus[j1];
                            v0 = __expf(-gma*t0*t0); v1 = __expf(-gma*t1*t1);
                        } else {
                            v0 = (j0 == 16 + ia || j0 == 32 + ic) ? 1.0f : 0.0f;
                            v1 = (j1 == 16 + ia || j1 == 32 + ic) ? 1.0f : 0.0f;
                        }
                        hp[p] = hpack2(v0, v1);
                    }
                    *(uint4*)(smc + RA(2) + (uint32_t)m*128
                              + (uint32_t)(((uint32_t)s ^ rxm) << 4)) = H;
                }
            }
        }
        const uint32_t Ab = sb + RA(s3);
        const uint32_t Bb = sb + RB(c & 1);
        {
            uint32_t aC[8], bF[3][4];
            ldsm4(aC,     Ab + aro0 + XA(0));
            ldsm4(aC + 4, Ab + aro1 + XA(0));
            ldsm4(bF[0], Bb + bro1 + XB(0));            // i=0: ks0 nt0
            ldsm4(bF[1], Bb + bro1 + 2048 + XB(0));     // i=1: ks0 nt1
            #pragma unroll
            for (int i = 0; i < 16; i++) {
                const int nt = i & 3;
                if (i < 14) {
                    const int ip = i + 2;
                    ldsm4(bF[ip % 3], Bb + bro1 + (uint32_t)(ip & 3)*2048 + XB(ip >> 2));
                }
                const uint32_t* bC = bF[i % 3];
                mma_h(acc[0][nt*2],   aC,     bC[0], bC[1]);
                mma_h(acc[0][nt*2+1], aC,     bC[2], bC[3]);
                mma_h(acc[1][nt*2],   aC + 4, bC[0], bC[1]);
                mma_h(acc[1][nt*2+1], aC + 4, bC[2], bC[3]);
                if (nt == 3 && i < 15) {
                    const int ks1 = (i + 1) >> 2;
                    ldsm4(aC,     Ab + aro0 + XA(ks1));
                    ldsm4(aC + 4, Ab + aro1 + XA(ks1));
                }
            }
        }
        __syncthreads();   // B stage c&1 fully consumed before overwrite
        if (c <= 6) {
            if (tid == 0) {
                MBAR_EXPECT(sb + MBAR + (c & 1)*8, 32768);
                bulk_g2s(sb + RB(c & 1), g_W1p + (size_t)(c + 2)*32768, 32768,
                         sb + MBAR + (c & 1)*8);
            }
        } else if (c == 7) {
            if (tid == 0) {
                #pragma unroll
                for (int s2 = 2; s2 < 4; s2++) {
                    MBAR_EXPECT(sb + MBAR + 16 + s2*8, 16384);
                    bulk_g2s(sb + B2SLOT(s2), g_W2p + (size_t)s2*16384, 16384,
                             sb + MBAR + 16 + s2*8);
                }
            }
        }
        s3 = (s3 == 2) ? 0 : s3 + 1;
    }

    // ================= epilogue 1: +b1, LN(256), SiLU -> A2 fp16 =================
    {
        const float* b1s  = (const float*)(smc + B1S);
        const float* g1s  = (const float*)(smc + G1S);
        const float* be1s = (const float*)(smc + BE1S);
        float* psum = (float*)(smc + PSUM);
        float* psq  = (float*)(smc + PSQ);
        const int g = lane >> 2, tig = lane & 3;
        float S[2][2] = {{0,0},{0,0}}, Q[2][2] = {{0,0},{0,0}};
        #pragma unroll
        for (int mb = 0; mb < 2; mb++)
            #pragma unroll
            for (int nt = 0; nt < 8; nt++) {
                const int n = warp_n*64 + nt*8 + tig*2;
                const float bn0 = b1s[n], bn1 = b1s[n+1];
                acc[mb][nt][0] += bn0; acc[mb][nt][1] += bn1;
                acc[mb][nt][2] += bn0; acc[mb][nt][3] += bn1;
                S[mb][0] += acc[mb][nt][0] + acc[mb][nt][1];
                Q[mb][0] += acc[mb][nt][0]*acc[mb][nt][0] + acc[mb][nt][1]*acc[mb][nt][1];
                S[mb][1] += acc[mb][nt][2] + acc[mb][nt][3];
                Q[mb][1] += acc[mb][nt][2]*acc[mb][nt][2] + acc[mb][nt][3]*acc[mb][nt][3];
            }
        #pragma unroll
        for (int off = 1; off <= 2; off <<= 1)
            #pragma unroll
            for (int mb = 0; mb < 2; mb++)
                #pragma unroll
                for (int hh = 0; hh < 2; hh++) {
                    S[mb][hh] += __shfl_xor_sync(~0u, S[mb][hh], off);
                    Q[mb][hh] += __shfl_xor_sync(~0u, Q[mb][hh], off);
                }
        if (tig == 0) {
            #pragma unroll
            for (int mb = 0; mb < 2; mb++)
                #pragma unroll
                for (int hh = 0; hh < 2; hh++) {
                    const int row = m0w + mb*16 + g + hh*8;
                    psum[row*4 + warp_n] = S[mb][hh];
                    psq[row*4 + warp_n]  = Q[mb][hh];
                }
        }
        __syncthreads();   // psum exchange; MMA(8) globally complete past here
        if (tid == 0) {
            #pragma unroll
            for (int s2 = 0; s2 < 2; s2++) {
                MBAR_EXPECT(sb + MBAR + 16 + s2*8, 16384);
                bulk_g2s(sb + B2SLOT(s2), g_W2p + (size_t)s2*16384, 16384,
                         sb + MBAR + 16 + s2*8);
            }
        }
        float mean[2][2], rstd[2][2];
        #pragma unroll
        for (int mb = 0; mb < 2; mb++)
            #pragma unroll
            for (int hh = 0; hh < 2; hh++) {
                const int row = m0w + mb*16 + g + hh*8;
                const float s4 = psum[row*4+0] + psum[row*4+1] + psum[row*4+2] + psum[row*4+3];
                const float q4 = psq[row*4+0] + psq[row*4+1] + psq[row*4+2] + psq[row*4+3];
                mean[mb][hh] = s4 * (1.0f/256.0f);
                rstd[mb][hh] = rsqrtf(q4 * (1.0f/256.0f) - mean[mb][hh]*mean[mb][hh] + LN_EPS);
            }
        #pragma unroll
        for (int mb = 0; mb < 2; mb++)
            #pragma unroll
            for (int nt = 0; nt < 8; nt++) {
                const int n = warp_n*64 + nt*8 + tig*2;
                const float ga = g1s[n], gb = g1s[n+1], ba = be1s[n], bb = be1s[n+1];
                #pragma unroll
                for (int hh = 0; hh < 2; hh++) {
                    const int row = m0w + mb*16 + g + hh*8;
                    const float v0 = silu_f((acc[mb][nt][hh*2+0] - mean[mb][hh])*rstd[mb][hh]*ga + ba);
                    const float v1 = silu_f((acc[mb][nt][hh*2+1] - mean[mb][hh])*rstd[mb][hh]*gb + bb);
                    const uint32_t ad = (uint32_t)A2CH(warp_n) + (uint32_t)row*128
                                        + (uint32_t)((nt ^ (row & 7)) << 4) + (uint32_t)tig*4;
                    *(uint32_t*)(smc + ad) = hpack2(v0, v1);
                }
            }
    }
    __syncthreads();   // A2 visible before layer-2 ldsm

    // ================= layer 2: distance-2 pipeline, slots {2,3,0,1} =============
    float acc2[2][4][4];
    #pragma unroll
    for (int a = 0; a < 2; a++)
        #pragma unroll
        for (int i = 0; i < 4; i++)
            #pragma unroll
            for (int j = 0; j < 4; j++) acc2[a][i][j] = 0.0f;

    const int order[4] = {2, 3, 0, 1};
    #pragma unroll
    for (int oi = 0; oi < 4; oi++) {
        const int c2 = order[oi];
        mbar_wait(sb + MBAR + 16 + c2*8, 0);
        const uint32_t Ab = sb + A2CH(c2);
        const uint32_t Bb = sb + B2SLOT(c2);
        uint32_t aC[8], bF[3][4];
        ldsm4(aC,     Ab + aro0 + XA(0));
        ldsm4(aC + 4, Ab + aro1 + XA(0));
        ldsm4(bF[0], Bb + bro2 + XB(0));           // i=0: ks0 nt0
        ldsm4(bF[1], Bb + bro2 + 2048 + XB(0));    // i=1: ks0 nt1
        #pragma unroll
        for (int i = 0; i < 8; i++) {              // ks = i>>1, nt = i&1
            const int nt = i & 1;
            if (i < 6) {
                const int ip = i + 2;
                ldsm4(bF[ip % 3], Bb + bro2 + (uint32_t)(ip & 1)*2048 + XB(ip >> 1));
            }
            const uint32_t* bC = bF[i % 3];
            mma_h(acc2[0][nt*2],   aC,     bC[0], bC[1]);
            mma_h(acc2[0][nt*2+1], aC,     bC[2], bC[3]);
            mma_h(acc2[1][nt*2],   aC + 4, bC[0], bC[1]);
            mma_h(acc2[1][nt*2+1], aC + 4, bC[2], bC[3]);
            if (nt == 1 && i < 7) {
                const int ks1 = (i + 1) >> 1;
                ldsm4(aC,     Ab + aro0 + XA(ks1));
                ldsm4(aC + 4, Ab + aro1 + XA(ks1));
            }
        }
    }

    // ========== epilogue 2: +b2, LN(128), SiLU, FUSED layer-3 partials ==========
    {
        const float* b2s  = (const float*)(smc + B2S);
        const float* g2s  = (const float*)(smc + G2S);
        const float* be2s = (const float*)(smc + BE2S);
        const float* w3s  = (const float*)(smc + W3S);
        float* psum = (float*)(smc + PSUM);
        float* psq  = (float*)(smc + PSQ);
        float* l3p  = (float*)(smc + L3P);
        const int g = lane >> 2, tig = lane & 3;
        float S[2][2] = {{0,0},{0,0}}, Q[2][2] = {{0,0},{0,0}};
        #pragma unroll
        for (int mb = 0; mb < 2; mb++)
            #pragma unroll
            for (int nt = 0; nt < 4; nt++) {
                const int n = warp_n*32 + nt*8 + tig*2;
                const float bn0 = b2s[n], bn1 = b2s[n+1];
                acc2[mb][nt][0] += bn0; acc2[mb][nt][1] += bn1;
                acc2[mb][nt][2] += bn0; acc2[mb][nt][3] += bn1;
                S[mb][0] += acc2[mb][nt][0] + acc2[mb][nt][1];
                Q[mb][0] += acc2[mb][nt][0]*acc2[mb][nt][0] + acc2[mb][nt][1]*acc2[mb][nt][1];
                S[mb][1] += acc2[mb][nt][2] + acc2[mb][nt][3];
                Q[mb][1] += acc2[mb][nt][2]*acc2[mb][nt][2] + acc2[mb][nt][3]*acc2[mb][nt][3];
            }
        #pragma unroll
        for (int off = 1; off <= 2; off <<= 1)
            #pragma unroll
            for (int mb = 0; mb < 2; mb++)
                #pragma unroll
                for (int hh = 0; hh < 2; hh++) {
                    S[mb][hh] += __shfl_xor_sync(~0u, S[mb][hh], off);
                    Q[mb][hh] += __shfl_xor_sync(~0u, Q[mb][hh], off);
                }
        if (tig == 0) {
            #pragma unroll
            for (int mb = 0; mb < 2; mb++)
                #pragma unroll
                for (int hh = 0; hh < 2; hh++) {
                    const int row = m0w + mb*16 + g + hh*8;
                    psum[row*4 + warp_n] = S[mb][hh];
                    psq[row*4 + warp_n]  = Q[mb][hh];
                }
        }
        __syncthreads();   // psum exchange; all layer-2 ldsm done -> L3P free
        float o[2][2][5];
        #pragma unroll
        for (int mb = 0; mb < 2; mb++)
            #pragma unroll
            for (int hh = 0; hh < 2; hh++)
                #pragma unroll
                for (int j = 0; j < 5; j++) o[mb][hh][j] = 0.0f;
        #pragma unroll
        for (int mb = 0; mb < 2; mb++)
            #pragma unroll
            for (int hh = 0; hh < 2; hh++) {
                const int row = m0w + mb*16 + g + hh*8;
                const float s4 = psum[row*4+0] + psum[row*4+1] + psum[row*4+2] + psum[row*4+3];
                const float q4 = psq[row*4+0] + psq[row*4+1] + psq[row*4+2] + psq[row*4+3];
                const float mean = s4 * (1.0f/128.0f);
                const float rstd = rsqrtf(q4 * (1.0f/128.0f) - mean*mean + LN_EPS);
                #pragma unroll
                for (int nt = 0; nt < 4; nt++) {
                    const int n = warp_n*32 + nt*8 + tig*2;
                    const float v0 = silu_f((acc2[mb][nt][hh*2+0] - mean)*rstd*g2s[n]   + be2s[n]);
                    const float v1 = silu_f((acc2[mb][nt][hh*2+1] - mean)*rstd*g2s[n+1] + be2s[n+1]);
                    const float* w0 = w3s + n*5;
                    #pragma unroll
                    for (int j = 0; j < 5; j++)
                        o[mb][hh][j] += v0*w0[j] + v1*w0[5 + j];
                }
            }
        #pragma unroll
        for (int off = 1; off <= 2; off <<= 1)
            #pragma unroll
            for (int mb = 0; mb < 2; mb++)
                #pragma unroll
                for (int hh = 0; hh < 2; hh++)
                    #pragma unroll
                    for (int j = 0; j < 5; j++)
                        o[mb][hh][j] += __shfl_xor_sync(~0u, o[mb][hh][j], off);
        if (tig == 0) {
            #pragma unroll
            for (int mb = 0; mb < 2; mb++)
                #pragma unroll
                for (int hh = 0; hh < 2; hh++) {
                    const int row = m0w + mb*16 + g + hh*8;
                    float* dst = l3p + row*20 + warp_n*5;
                    #pragma unroll
                    for (int j = 0; j < 5; j++) dst[j] = o[mb][hh][j];
                }
        }
    }
    __syncthreads();

    // ---- final: sum 4 warp-partials + b3, store ----
    if (tid < MT && tid < mcount) {
        const float* l3p = (const float*)(smc + L3P);
        const float* b3s = (const float*)(smc + B3S);
        const float* pr  = l3p + tid*20;
        float* op = out + (size_t)(e0 + tid)*5;
        #pragma unroll
        for (int j = 0; j < 5; j++)
            op[j] = b3s[j] + pr[j] + pr[5 + j] + pr[10 + j] + pr[15 + j];
    }
    #undef XA
    #undef XB
}

extern "C" void kernel_launch(void* const* d_in, const int* in_sizes, int n_in,
                              void* d_out, int out_size)
{
    const float* h         = (const float*)d_in[0];
    const float* x         = (const float*)d_in[1];
    const int*   spawn_idx = (const int*)d_in[2];
    const int*   exist_idx = (const int*)d_in[3];
    const float* ins_x     = (const float*)d_in[4];
    const int*   ins_a     = (const int*)d_in[5];
    const int*   ins_c     = (const int*)d_in[6];
    const float* W1        = (const float*)d_in[7];
    const float* b1        = (const float*)d_in[8];
    const float* g1        = (const float*)d_in[9];
    const float* be1       = (const float*)d_in[10];
    const float* W2        = (const float*)d_in[11];
    const float* b2        = (const float*)d_in[12];
    const float* g2        = (const float*)d_in[13];
    const float* be2       = (const float*)d_in[14];
    const float* W3        = (const float*)d_in[15];
    const float* b3        = (const float*)d_in[16];
    const float* rbf_mu    = (const float*)d_in[17];
    const float* rbf_gamma = (const float*)d_in[18];
    float* out = (float*)d_out;

    prep_h<<<NNODES*32/256, 256>>>(h);
    prep_w<<<(9*256*8 + 4*128*8 + 255)/256, 256>>>(W1, W2);
    pad_launch_k<<<1, 32>>>();

    cudaFuncSetAttribute(edgehead_mma,
                         cudaFuncAttributeMaxDynamicSharedMemorySize, SMEM_TOTAL);
    const int grid = (E_TOTAL + MT - 1) / MT;   // 7813
    edgehead_mma<<<grid, NTHR, SMEM_TOTAL>>>(
        x, spawn_idx, exist_idx, ins_x, ins_a, ins_c,
        b1, g1, be1, b2, g2, be2, W3, b3, rbf_mu, rbf_gamma, out);
}